// round 2
// baseline (speedup 1.0000x reference)
#include <cuda_runtime.h>
#include <cuda_bf16.h>
#include <cfloat>

// Problem constants (fixed shapes from setup_inputs)
#define B_  4
#define H_  160
#define W_  160
#define D_  160
#define VOL_ (H_*W_*D_)          // 4,096,000
#define TOTAL_ (B_*VOL_)         // 16,384,000
#define VPT_ 4                   // voxels per thread (along d), D_ % VPT_ == 0

// Scratch: per-batch theta (3x4 row-major) and encoded min (fill) value.
__device__ float    g_theta[B_][12];
__device__ unsigned g_fill_bits[B_];

// Monotone float->uint encoding so unsigned atomicMin == float min.
__device__ __forceinline__ unsigned enc_f(float f) {
    unsigned u = __float_as_uint(f);
    return (u & 0x80000000u) ? ~u : (u | 0x80000000u);
}
__device__ __forceinline__ float dec_f(unsigned e) {
    unsigned u = (e & 0x80000000u) ? (e & 0x7FFFFFFFu) : ~e;
    return __uint_as_float(u);
}

// ---------------------------------------------------------------------------
// Kernel 1: per-batch setup — quaternion -> rotation matrix + translation,
// and reset of the fill-min accumulators. 1 thread per batch.
// ---------------------------------------------------------------------------
__global__ void st3d_init_kernel(const float* __restrict__ transfos) {
    int b = threadIdx.x;
    if (b >= B_) return;
    g_fill_bits[b] = 0xFFFFFFFFu;   // encodes "larger than any finite float"

    const float* q = transfos + b * 7;
    float x = q[0], y = q[1], z = q[2], w = q[3];
    float tx = 2.0f * x, ty = 2.0f * y, tz = 2.0f * z;
    float twx = tx * w, twy = ty * w, twz = tz * w;
    float txx = tx * x, txy = ty * x, txz = tz * x;
    float tyy = ty * y, tyz = tz * y, tzz = tz * z;

    float* T = g_theta[b];
    T[0]  = 1.0f - (tyy + tzz);
    T[1]  = txy - twz;
    T[2]  = txz + twy;
    T[3]  = q[4];
    T[4]  = txy + twz;
    T[5]  = 1.0f - (txx + tzz);
    T[6]  = tyz - twx;
    T[7]  = q[5];
    T[8]  = txz - twy;
    T[9]  = tyz + twx;
    T[10] = 1.0f - (txx + tyy);
    T[11] = q[6];
}

// ---------------------------------------------------------------------------
// Kernel 2: per-batch global min of the image (fill value).
// float4 vectorized grid-stride, warp-shuffle reduce, one atomicMin per block.
// ---------------------------------------------------------------------------
__global__ void st3d_min_kernel(const float* __restrict__ img) {
    const int b = blockIdx.y;
    const float4* p = reinterpret_cast<const float4*>(img + (size_t)b * VOL_);
    const int n4 = VOL_ / 4;   // 1,024,000

    float m = FLT_MAX;
    for (int i = blockIdx.x * blockDim.x + threadIdx.x; i < n4;
         i += gridDim.x * blockDim.x) {
        float4 v = p[i];
        m = fminf(m, fminf(fminf(v.x, v.y), fminf(v.z, v.w)));
    }
    #pragma unroll
    for (int o = 16; o > 0; o >>= 1)
        m = fminf(m, __shfl_xor_sync(0xFFFFFFFFu, m, o));

    __shared__ float sm[32];
    int lane = threadIdx.x & 31;
    int wid  = threadIdx.x >> 5;
    if (lane == 0) sm[wid] = m;
    __syncthreads();
    if (wid == 0) {
        int nwarp = blockDim.x >> 5;
        m = (lane < nwarp) ? sm[lane] : FLT_MAX;
        #pragma unroll
        for (int o = 16; o > 0; o >>= 1)
            m = fminf(m, __shfl_xor_sync(0xFFFFFFFFu, m, o));
        if (lane == 0) atomicMin(&g_fill_bits[b], enc_f(m));
    }
}

// ---------------------------------------------------------------------------
// Kernel 3: main sampling kernel. VPT_=4 consecutive d-voxels per thread,
// float4 coalesced store. Output: out[((b*H + h)*W + w)*D + d].
// ---------------------------------------------------------------------------
__global__ void __launch_bounds__(256)
st3d_sample_kernel(const float* __restrict__ img, float* __restrict__ out) {
    int t = blockIdx.x * blockDim.x + threadIdx.x;      // one thread per 4 voxels
    if (t >= TOTAL_ / VPT_) return;

    int dq = t % (D_ / VPT_);          // d-group index; d0 = dq*VPT_
    int t1 = t / (D_ / VPT_);
    int w  = t1 % W_;
    int t2 = t1 / W_;
    int h  = t2 % H_;
    int b  = t2 / H_;
    int d0 = dq * VPT_;

    // Normalized coords in [-1, 1]
    const float step = 2.0f / 159.0f;
    float x = fmaf((float)w,  step, -1.0f);
    float y = fmaf((float)h,  step, -1.0f);
    float z = fmaf((float)d0, step, -1.0f);

    const float* T = g_theta[b];
    float T0 = T[0], T1 = T[1], T2  = T[2],  T3  = T[3];
    float T4 = T[4], T5 = T[5], T6  = T[6],  T7  = T[7];
    float T8 = T[8], T9 = T[9], T10 = T[10], T11 = T[11];

    // Sample point for the first voxel; per-d-step increment vector.
    float px = fmaf(T0, x, fmaf(T1, y, fmaf(T2,  z, T3)));
    float py = fmaf(T4, x, fmaf(T5, y, fmaf(T6,  z, T7)));
    float pz = fmaf(T8, x, fmaf(T9, y, fmaf(T10, z, T11)));

    const float c = 79.5f;             // (160-1)/2: ix = c*px + c
    float ix = fmaf(c, px, c);
    float iy = fmaf(c, py, c);
    float iz = fmaf(c, pz, c);
    float dxs = c * step * T2;         // d(ix)/d(d-step)
    float dys = c * step * T6;
    float dzs = c * step * T10;

    const float* im = img + (size_t)b * VOL_;
    float fill = dec_f(g_fill_bits[b]);
    float res[VPT_];

    #pragma unroll
    for (int k = 0; k < VPT_; k++) {
        bool valid = (ix >= 0.0f) & (ix <= 159.0f) &
                     (iy >= 0.0f) & (iy <= 159.0f) &
                     (iz >= 0.0f) & (iz <= 159.0f);

        float fx = fminf(fmaxf(floorf(ix), 0.0f), 159.0f);
        float fy = fminf(fmaxf(floorf(iy), 0.0f), 159.0f);
        float fz = fminf(fmaxf(floorf(iz), 0.0f), 159.0f);

        float ax = fminf(fmaxf(ix - fx, 0.0f), 1.0f);
        float ay = fminf(fmaxf(iy - fy, 0.0f), 1.0f);
        float az = fminf(fmaxf(iz - fz, 0.0f), 1.0f);
        float wx0 = 1.0f - ax, wx1 = ax;
        float wy0 = 1.0f - ay, wy1 = ay;
        float wz0 = 1.0f - az, wz1 = az;

        int x0 = (int)fx, y0 = (int)fy, z0 = (int)fz;
        int x1 = min(x0 + 1, 159);
        int y1 = min(y0 + 1, 159);
        int z1 = min(z0 + 1, 159);

        // img layout (H, W, D): idx = (h*W + w)*D + d, sampled at (gy, gx, gz)
        int r00 = (y0 * W_ + x0) * D_;
        int r01 = (y1 * W_ + x0) * D_;
        int r10 = (y0 * W_ + x1) * D_;
        int r11 = (y1 * W_ + x1) * D_;

        float v000 = __ldg(im + r00 + z0);
        float v001 = __ldg(im + r00 + z1);
        float v010 = __ldg(im + r01 + z0);
        float v011 = __ldg(im + r01 + z1);
        float v100 = __ldg(im + r10 + z0);
        float v101 = __ldg(im + r10 + z1);
        float v110 = __ldg(im + r11 + z0);
        float v111 = __ldg(im + r11 + z1);

        float acc = 0.0f;
        acc = fmaf(wx0 * wy0 * wz0, v000, acc);
        acc = fmaf(wx0 * wy0 * wz1, v001, acc);
        acc = fmaf(wx0 * wy1 * wz0, v010, acc);
        acc = fmaf(wx0 * wy1 * wz1, v011, acc);
        acc = fmaf(wx1 * wy0 * wz0, v100, acc);
        acc = fmaf(wx1 * wy0 * wz1, v101, acc);
        acc = fmaf(wx1 * wy1 * wz0, v110, acc);
        acc = fmaf(wx1 * wy1 * wz1, v111, acc);

        res[k] = valid ? acc : fill;

        ix += dxs; iy += dys; iz += dzs;
    }

    float4 o4 = make_float4(res[0], res[1], res[2], res[3]);
    size_t oidx = ((size_t)(b * H_ + h) * W_ + w) * D_ + d0;
    *reinterpret_cast<float4*>(out + oidx) = o4;
}

// ---------------------------------------------------------------------------
extern "C" void kernel_launch(void* const* d_in, const int* in_sizes, int n_in,
                              void* d_out, int out_size) {
    const float* img      = (const float*)d_in[0];
    const float* transfos = (const float*)d_in[1];
    float*       out      = (float*)d_out;

    st3d_init_kernel<<<1, 32>>>(transfos);

    dim3 mgrid(2048, B_);
    st3d_min_kernel<<<mgrid, 256>>>(img);

    int threads = 256;
    int nthreads_total = TOTAL_ / VPT_;                 // 4,096,000
    int blocks = (nthreads_total + threads - 1) / threads;  // 16000
    st3d_sample_kernel<<<blocks, threads>>>(img, out);
}

// round 6
// speedup vs baseline: 4.0263x; 4.0263x over previous
#include <cuda_runtime.h>
#include <cuda_bf16.h>
#include <cfloat>

// Problem constants (fixed shapes from setup_inputs)
#define B_  4
#define H_  160
#define W_  160
#define D_  160
#define VOL_ (H_*W_*D_)          // 4,096,000
#define TOTAL_ (B_*VOL_)         // 16,384,000
#define VPT_ 8                   // voxels per thread (along d), D_ % VPT_ == 0

// Scratch: per-batch theta (3x4 row-major) and encoded min (fill) value.
__device__ float    g_theta[B_][12];
__device__ unsigned g_fill_bits[B_];

// Monotone float->uint encoding so unsigned atomicMin == float min.
__device__ __forceinline__ unsigned enc_f(float f) {
    unsigned u = __float_as_uint(f);
    return (u & 0x80000000u) ? ~u : (u | 0x80000000u);
}
__device__ __forceinline__ float dec_f(unsigned e) {
    unsigned u = (e & 0x80000000u) ? (e & 0x7FFFFFFFu) : ~e;
    return __uint_as_float(u);
}

// ---------------------------------------------------------------------------
// Kernel 1: per-batch setup — quaternion -> rotation matrix + translation,
// and reset of the fill-min accumulators. 1 thread per batch.
// ---------------------------------------------------------------------------
__global__ void st3d_init_kernel(const float* __restrict__ transfos) {
    int b = threadIdx.x;
    if (b >= B_) return;
    g_fill_bits[b] = 0xFFFFFFFFu;   // encodes "larger than any finite float"

    const float* q = transfos + b * 7;
    float x = q[0], y = q[1], z = q[2], w = q[3];
    float tx = 2.0f * x, ty = 2.0f * y, tz = 2.0f * z;
    float twx = tx * w, twy = ty * w, twz = tz * w;
    float txx = tx * x, txy = ty * x, txz = tz * x;
    float tyy = ty * y, tyz = tz * y, tzz = tz * z;

    float* T = g_theta[b];
    T[0]  = 1.0f - (tyy + tzz);
    T[1]  = txy - twz;
    T[2]  = txz + twy;
    T[3]  = q[4];
    T[4]  = txy + twz;
    T[5]  = 1.0f - (txx + tzz);
    T[6]  = tyz - twx;
    T[7]  = q[5];
    T[8]  = txz - twy;
    T[9]  = tyz + twx;
    T[10] = 1.0f - (txx + tyy);
    T[11] = q[6];
}

// ---------------------------------------------------------------------------
// Kernel 2: per-batch global min of the image (fill value).
// float4 vectorized grid-stride (streaming loads), warp-shuffle reduce,
// one atomicMin per block.
// ---------------------------------------------------------------------------
__global__ void st3d_min_kernel(const float* __restrict__ img) {
    const int b = blockIdx.y;
    const float4* p = reinterpret_cast<const float4*>(img + (size_t)b * VOL_);
    const int n4 = VOL_ / 4;   // 1,024,000

    float m = FLT_MAX;
    for (int i = blockIdx.x * blockDim.x + threadIdx.x; i < n4;
         i += gridDim.x * blockDim.x) {
        float4 v = __ldcs(p + i);   // streaming: don't evict reused lines
        m = fminf(m, fminf(fminf(v.x, v.y), fminf(v.z, v.w)));
    }
    #pragma unroll
    for (int o = 16; o > 0; o >>= 1)
        m = fminf(m, __shfl_xor_sync(0xFFFFFFFFu, m, o));

    __shared__ float sm[32];
    int lane = threadIdx.x & 31;
    int wid  = threadIdx.x >> 5;
    if (lane == 0) sm[wid] = m;
    __syncthreads();
    if (wid == 0) {
        int nwarp = blockDim.x >> 5;
        m = (lane < nwarp) ? sm[lane] : FLT_MAX;
        #pragma unroll
        for (int o = 16; o > 0; o >>= 1)
            m = fminf(m, __shfl_xor_sync(0xFFFFFFFFu, m, o));
        if (lane == 0) atomicMin(&g_fill_bits[b], enc_f(m));
    }
}

// ---------------------------------------------------------------------------
// Kernel 3: main sampling kernel. VPT_=8 consecutive d-voxels per thread,
// two float4 streaming stores. Skips all gather work for out-of-range voxels
// (the common case: unnormalized quaternions -> |A| ~ 4 -> most points
// land outside [-1,1]^3 and take the fill value).
// ---------------------------------------------------------------------------
__global__ void __launch_bounds__(256)
st3d_sample_kernel(const float* __restrict__ img, float* __restrict__ out) {
    int t = blockIdx.x * blockDim.x + threadIdx.x;      // one thread per 8 voxels
    if (t >= TOTAL_ / VPT_) return;

    int dq = t % (D_ / VPT_);          // d-group index; d0 = dq*VPT_
    int t1 = t / (D_ / VPT_);
    int w  = t1 % W_;
    int t2 = t1 / W_;
    int h  = t2 % H_;
    int b  = t2 / H_;
    int d0 = dq * VPT_;

    // Normalized coords in [-1, 1]
    const float step = 2.0f / 159.0f;
    float x = fmaf((float)w,  step, -1.0f);
    float y = fmaf((float)h,  step, -1.0f);
    float z = fmaf((float)d0, step, -1.0f);

    const float4* Tv = reinterpret_cast<const float4*>(g_theta[b]);
    float4 R0 = __ldg(Tv + 0);   // T0..T3
    float4 R1 = __ldg(Tv + 1);   // T4..T7
    float4 R2 = __ldg(Tv + 2);   // T8..T11

    // Sample point for the first voxel; per-d-step increment vector.
    float px = fmaf(R0.x, x, fmaf(R0.y, y, fmaf(R0.z, z, R0.w)));
    float py = fmaf(R1.x, x, fmaf(R1.y, y, fmaf(R1.z, z, R1.w)));
    float pz = fmaf(R2.x, x, fmaf(R2.y, y, fmaf(R2.z, z, R2.w)));

    const float c = 79.5f;             // (160-1)/2: ix = c*px + c
    float ix = fmaf(c, px, c);
    float iy = fmaf(c, py, c);
    float iz = fmaf(c, pz, c);
    float dxs = c * step * R0.z;       // d(ix)/d(d-step)
    float dys = c * step * R1.z;
    float dzs = c * step * R2.z;

    float fill = dec_f(g_fill_bits[b]);
    size_t oidx = ((size_t)(b * H_ + h) * W_ + w) * D_ + d0;
    float4* o4p = reinterpret_cast<float4*>(out + oidx);

    // Group-level early out: bounding interval over the 8 d-steps.
    {
        const float span = (float)(VPT_ - 1);
        float ix_lo = fminf(ix, ix + span * dxs), ix_hi = fmaxf(ix, ix + span * dxs);
        float iy_lo = fminf(iy, iy + span * dys), iy_hi = fmaxf(iy, iy + span * dys);
        float iz_lo = fminf(iz, iz + span * dzs), iz_hi = fmaxf(iz, iz + span * dzs);
        bool any_possible = (ix_hi >= 0.0f) & (ix_lo <= 159.0f) &
                            (iy_hi >= 0.0f) & (iy_lo <= 159.0f) &
                            (iz_hi >= 0.0f) & (iz_lo <= 159.0f);
        if (!any_possible) {
            float4 f4 = make_float4(fill, fill, fill, fill);
            __stcs(o4p + 0, f4);
            __stcs(o4p + 1, f4);
            return;
        }
    }

    const float* im = img + (size_t)b * VOL_;
    float res[VPT_];

    #pragma unroll
    for (int k = 0; k < VPT_; k++) {
        bool valid = (ix >= 0.0f) & (ix <= 159.0f) &
                     (iy >= 0.0f) & (iy <= 159.0f) &
                     (iz >= 0.0f) & (iz <= 159.0f);

        if (valid) {
            // In-range: round-down conversion == floor, frac in [0,1);
            // the reference's clips are identities here.
            int x0 = __float2int_rd(ix);
            int y0 = __float2int_rd(iy);
            int z0 = __float2int_rd(iz);
            float ax = ix - (float)x0;
            float ay = iy - (float)y0;
            float az = iz - (float)z0;
            float wx0 = 1.0f - ax, wx1 = ax;
            float wy0 = 1.0f - ay, wy1 = ay;
            float wz0 = 1.0f - az, wz1 = az;

            int x1 = min(x0 + 1, 159);
            int y1 = min(y0 + 1, 159);
            int z1 = min(z0 + 1, 159);

            // img layout (H, W, D): idx = (h*W + w)*D + d, sampled (gy, gx, gz)
            int r00 = (y0 * W_ + x0) * D_;
            int r01 = (y1 * W_ + x0) * D_;
            int r10 = (y0 * W_ + x1) * D_;
            int r11 = (y1 * W_ + x1) * D_;

            float v000 = __ldg(im + r00 + z0);
            float v001 = __ldg(im + r00 + z1);
            float v010 = __ldg(im + r01 + z0);
            float v011 = __ldg(im + r01 + z1);
            float v100 = __ldg(im + r10 + z0);
            float v101 = __ldg(im + r10 + z1);
            float v110 = __ldg(im + r11 + z0);
            float v111 = __ldg(im + r11 + z1);

            float acc = 0.0f;
            acc = fmaf(wx0 * wy0 * wz0, v000, acc);
            acc = fmaf(wx0 * wy0 * wz1, v001, acc);
            acc = fmaf(wx0 * wy1 * wz0, v010, acc);
            acc = fmaf(wx0 * wy1 * wz1, v011, acc);
            acc = fmaf(wx1 * wy0 * wz0, v100, acc);
            acc = fmaf(wx1 * wy0 * wz1, v101, acc);
            acc = fmaf(wx1 * wy1 * wz0, v110, acc);
            acc = fmaf(wx1 * wy1 * wz1, v111, acc);
            res[k] = acc;
        } else {
            res[k] = fill;
        }

        ix += dxs; iy += dys; iz += dzs;
    }

    __stcs(o4p + 0, make_float4(res[0], res[1], res[2], res[3]));
    __stcs(o4p + 1, make_float4(res[4], res[5], res[6], res[7]));
}

// ---------------------------------------------------------------------------
extern "C" void kernel_launch(void* const* d_in, const int* in_sizes, int n_in,
                              void* d_out, int out_size) {
    const float* img      = (const float*)d_in[0];
    const float* transfos = (const float*)d_in[1];
    float*       out      = (float*)d_out;

    st3d_init_kernel<<<1, 32>>>(transfos);

    dim3 mgrid(2048, B_);
    st3d_min_kernel<<<mgrid, 256>>>(img);

    int threads = 256;
    int nthreads_total = TOTAL_ / VPT_;                 // 2,048,000
    int blocks = (nthreads_total + threads - 1) / threads;  // 8000
    st3d_sample_kernel<<<blocks, threads>>>(img, out);
}